// round 13
// baseline (speedup 1.0000x reference)
#include <cuda_runtime.h>
#include <math.h>
#include <stdint.h>

#define LDIM 512
#define BDIM 64
#define CDIM 512
#define RANKS 8
#define COLS 64           // alpha columns per rank (= E rows per rank)
#define GRPB 4            // batches per cluster
#define NCL  16           // clusters

__device__ float g_logz[BDIM];
__device__ float g_scorep[BDIM];

// ---------------------------------------------------------------------------
__device__ __forceinline__ unsigned smem_u32(const void* p) {
    return (unsigned)__cvta_generic_to_shared(p);
}
__device__ __forceinline__ unsigned mapa_rank(unsigned saddr, unsigned rank) {
    unsigned r;
    asm("mapa.shared::cluster.u32 %0, %1, %2;" : "=r"(r) : "r"(saddr), "r"(rank));
    return r;
}
__device__ __forceinline__ void stc_f32(unsigned saddr, float v) {
    asm volatile("st.shared::cluster.f32 [%0], %1;" :: "r"(saddr), "f"(v) : "memory");
}
__device__ __forceinline__ void stc_v4(unsigned saddr, float4 v) {
    asm volatile("st.shared::cluster.v4.f32 [%0], {%1,%2,%3,%4};"
                 :: "r"(saddr), "f"(v.x), "f"(v.y), "f"(v.z), "f"(v.w) : "memory");
}
__device__ __forceinline__ void stc_2u64(unsigned saddr, unsigned long long a,
                                         unsigned long long b) {
    asm volatile("st.shared::cluster.v2.u64 [%0], {%1,%2};"
                 :: "r"(saddr), "l"(a), "l"(b) : "memory");
}
__device__ __forceinline__ void cluster_sync_() {
    asm volatile("barrier.cluster.arrive.aligned;" ::: "memory");
    asm volatile("barrier.cluster.wait.aligned;"   ::: "memory");
}
__device__ __forceinline__ unsigned long long ffma2(unsigned long long a,
                                                    unsigned long long b,
                                                    unsigned long long c) {
    unsigned long long d;
    asm("fma.rn.f32x2 %0, %1, %2, %3;" : "=l"(d) : "l"(a), "l"(b), "l"(c));
    return d;
}
__device__ __forceinline__ unsigned long long add2(unsigned long long a,
                                                   unsigned long long b) {
    unsigned long long d;
    asm("add.rn.f32x2 %0, %1, %2;" : "=l"(d) : "l"(a), "l"(b));
    return d;
}
__device__ __forceinline__ void mbar_init(unsigned addr, unsigned cnt) {
    asm volatile("mbarrier.init.shared.b64 [%0], %1;" :: "r"(addr), "r"(cnt) : "memory");
}
__device__ __forceinline__ void mbar_arrive_remote(unsigned addr) {
    asm volatile("mbarrier.arrive.release.cluster.shared::cluster.b64 _, [%0];"
                 :: "r"(addr) : "memory");
}
__device__ __forceinline__ void mbar_wait_acq(unsigned addr, unsigned parity) {
    unsigned done;
    asm volatile(
        "{\n\t.reg .pred p;\n\t"
        "mbarrier.try_wait.parity.acquire.cluster.shared::cta.b64 p, [%1], %2;\n\t"
        "selp.b32 %0, 1, 0, p;\n\t}"
        : "=r"(done) : "r"(addr), "r"(parity) : "memory");
    if (!done) {
        asm volatile(
            "{\n\t.reg .pred P1;\n\t"
            "WL_%=:\n\t"
            "mbarrier.try_wait.parity.acquire.cluster.shared::cta.b64 P1, [%0], %1, 0x989680;\n\t"
            "@P1 bra.uni WD_%=;\n\t"
            "bra.uni WL_%=;\n\t"
            "WD_%=:\n\t}"
            :: "r"(addr), "r"(parity) : "memory");
    }
}
__device__ __forceinline__ int mask_byte_probe(const unsigned char* m8) {
    int allnz = 1;
    for (int b = 0; b < BDIM; b++) if (m8[b] == 0) allnz = 0;
    return allnz;
}
__device__ __forceinline__ int get_mask2(const void* mask, int idx, int isbyte) {
    if (isbyte) return ((const unsigned char*)mask)[idx] != 0;
    return ((const int*)mask)[idx] != 0;
}

// ---------------------------------------------------------------------------
struct __align__(16) SM {
    float E[COLS * CDIM];                // 128 KB: my 64 rows x all 512 cols
    float2 stage2[COLS][GRPB];           // 2 KB: p for my rows, pre-duplicated {p,p}
    unsigned long long part1[256][GRPB]; // 8 KB: row-half-1 partials
    float2 inbox[2][RANKS][32][GRPB];    // 16 KB: incoming partials [par][src][cpl][g]
    float pmail[2][RANKS][GRPB];         // 256 B: lagged local maxes
    float wred[8];
    float wsum[8];
    float fm[RANKS][GRPB], fs[RANKS][GRPB];
    unsigned long long mbar[2];          // count 16 per parity
    unsigned char act4[LDIM][GRPB];
    unsigned char any[LDIM];
    int isbyte;
};

__global__ void __cluster_dims__(RANKS, 1, 1) __launch_bounds__(512, 1)
forward_kernel(const float* __restrict__ emit,
               const void*  __restrict__ mask,
               const float* __restrict__ trans,
               const float* __restrict__ tfs,
               const float* __restrict__ tte)
{
    extern __shared__ char smraw[];
    SM* sm = (SM*)smraw;

    const int t     = threadIdx.x;
    const int cta   = blockIdx.x;
    const int rank  = cta & (RANKS - 1);
    const int cl    = cta >> 3;
    const int bbase = cl * GRPB;

    const int g    = (t >> 6) & 3;        // owner batch (t<256)
    const int col  = t & 63;              // owner local column (= my E-row index)
    const int cg_glob = rank * COLS + col;
    const int lane = t & 31;
    const int wrp  = t >> 5;

    const int h = t >> 8;                 // matvec row half (0: rows 0-31, 1: 32-63)
    const int q = t & 255;                // matvec col-pair (cols 2q, 2q+1)

    if (t == 0) {
        sm->isbyte = mask_byte_probe((const unsigned char*)mask);
        mbar_init(smem_u32(&sm->mbar[0]), 16);
        mbar_init(smem_u32(&sm->mbar[1]), 16);
    }

    // ---- E slice: my 64 rows x all 512 cols: E[lr][c] = exp(trans[rank*64+lr][c])
    for (int idx = t; idx < COLS * CDIM; idx += 512)
        sm->E[idx] = expf(trans[(size_t)rank * COLS * CDIM + idx]);
    __syncthreads();

    // ---- mask flags (one i per thread) ----
    const int isbyte = sm->isbyte;
    {
        int i = t;
        int anyv = 0;
        #pragma unroll
        for (int gg = 0; gg < GRPB; gg++) {
            int m = get_mask2(mask, i * BDIM + bbase + gg, isbyte);
            sm->act4[i][gg] = (unsigned char)m;
            anyv |= m;
        }
        sm->any[i] = (unsigned char)anyv;
    }

    // ---- alpha_0 + warp maxes ----
    float a = 0.f, m_used = 0.f;
    if (t < 256) {
        a = emit[(size_t)(bbase + g) * CDIM + cg_glob] + tfs[cg_glob];
        float m = a;
        #pragma unroll
        for (int o = 16; o; o >>= 1) m = fmaxf(m, __shfl_xor_sync(0xffffffffu, m, o));
        if (lane == 0) sm->wred[wrp] = m;
    }
    __syncthreads();

    // ---- prologue: exact global max of alpha_0 (also publishes mbar inits) ----
    if (t < 32) {
        int dr = t >> 2, dg = t & 3;
        float ml = fmaxf(sm->wred[2 * dg], sm->wred[2 * dg + 1]);
        stc_f32(mapa_rank(smem_u32(&sm->fm[0][0]), dr) + (unsigned)((rank * 4 + dg) * 4), ml);
    }
    cluster_sync_();
    if (t < 256) {
        float mg = sm->fm[0][g];
        #pragma unroll
        for (int r = 1; r < RANKS; r++) mg = fmaxf(mg, sm->fm[r][g]);
        m_used = mg;
        float p = __expf(a - mg);
        sm->stage2[col][g] = make_float2(p, p);
    }
    __syncthreads();

    // per-warp push targets
    unsigned inb_dst = 0, pb_dst = 0;          // partial-push warps (0..7)
    if (wrp < 8) {
        inb_dst = mapa_rank(smem_u32(&sm->inbox[0][0][0][0]), wrp);
        pb_dst  = mapa_rank(smem_u32(&sm->mbar[0]), wrp);
    }
    unsigned pm_dst = 0, bm_dst = 0;           // mail warp (warp 8, lanes 0..7)
    if (wrp == 8 && lane < 8) {
        pm_dst = mapa_rank(smem_u32(&sm->pmail[0][0][0]), lane);
        bm_dst = mapa_rank(smem_u32(&sm->mbar[0]), lane);
    }

    int uses = 0;
    for (int i = 1; i < LDIM; i++) {
        if (!sm->any[i]) continue;
        const int par = uses & 1, ph = (uses >> 1) & 1;

        // ---- mail: warp 8 ships my current local maxes to all ranks ----
        if (wrp == 8 && lane < 8) {
            float4 mv = make_float4(fmaxf(sm->wred[0], sm->wred[1]),
                                    fmaxf(sm->wred[2], sm->wred[3]),
                                    fmaxf(sm->wred[4], sm->wred[5]),
                                    fmaxf(sm->wred[6], sm->wred[7]));
            stc_v4(pm_dst + (unsigned)((par * RANKS + rank) * 16), mv);
            mbar_arrive_remote(bm_dst + (unsigned)(par * 8));
        }

        // emit prefetch (consumed in combine)
        float e_reg = 0.f;
        if (t < 256) e_reg = emit[((size_t)i * BDIM + bbase + g) * CDIM + cg_glob];

        // ---- matvec from LOCAL p: my rows x all cols, 4 batches ----
        unsigned long long ac0 = 0, ac1 = 0, ac2 = 0, ac3 = 0;
        {
            const unsigned long long* Erow =
                (const unsigned long long*)sm->E + h * 32 * 256 + q;
            const ulonglong2* st2 = (const ulonglong2*)&sm->stage2[h * 32][0];
            #pragma unroll
            for (int c = 0; c < 32; c++) {
                unsigned long long e = Erow[c * 256];
                ulonglong2 pA = st2[c * 2], pB = st2[c * 2 + 1];
                ac0 = ffma2(pA.x, e, ac0);
                ac1 = ffma2(pA.y, e, ac1);
                ac2 = ffma2(pB.x, e, ac2);
                ac3 = ffma2(pB.y, e, ac3);
            }
        }
        if (h == 1) {
            *(ulonglong2*)&sm->part1[q][0] = make_ulonglong2(ac0, ac1);
            *(ulonglong2*)&sm->part1[q][2] = make_ulonglong2(ac2, ac3);
        }
        __syncthreads();

        // ---- h0: add halves, push partials to column owner (rank = wrp) ----
        if (h == 0) {
            ulonglong2 pA = *(const ulonglong2*)&sm->part1[q][0];
            ulonglong2 pB = *(const ulonglong2*)&sm->part1[q][2];
            ac0 = add2(ac0, pA.x); ac1 = add2(ac1, pA.y);
            ac2 = add2(ac2, pB.x); ac3 = add2(ac3, pB.y);
            unsigned off = (unsigned)(par * 8192 + rank * 1024 + (q & 31) * 32);
            stc_2u64(inb_dst + off,      ac0, ac1);
            stc_2u64(inb_dst + off + 16, ac2, ac3);
            __syncwarp();
            if (lane == 0) mbar_arrive_remote(pb_dst + (unsigned)(par * 8));
        }

        // ---- wait: all 8 partials + all 8 mails for this step ----
        mbar_wait_acq(smem_u32(&sm->mbar[par]), (unsigned)ph);

        // ---- combine: sum 8 rank-partials, update alpha, stage next p ----
        if (t < 256) {
            const float* ib = (const float*)&sm->inbox[par][0][0][0];
            int o = (col >> 1) * 8 + g * 2 + (col & 1);
            float s = ((ib[o]          + ib[o + 256])  + (ib[o + 512]  + ib[o + 768]))
                    + ((ib[o + 1024]   + ib[o + 1280]) + (ib[o + 1536] + ib[o + 1792]));
            float m_next = sm->pmail[par][0][g];
            #pragma unroll
            for (int r = 1; r < RANKS; r++) m_next = fmaxf(m_next, sm->pmail[par][r][g]);
            float anew = m_used + __logf(s) + e_reg;
            if (sm->act4[i][g]) a = anew;
            m_used = m_next;
            float p = __expf(a - m_next);
            sm->stage2[col][g] = make_float2(p, p);
            float m = a;
            #pragma unroll
            for (int o2 = 16; o2; o2 >>= 1) m = fmaxf(m, __shfl_xor_sync(0xffffffffu, m, o2));
            if (lane == 0) sm->wred[wrp] = m;
        }
        __syncthreads();
        uses++;
    }

    // ---- final: log_z = logsumexp(alpha + tte) across 8 ranks ----
    float v = -3.4e38f;
    if (t < 256) v = a + tte[cg_glob];
    {
        float m = v;
        #pragma unroll
        for (int o = 16; o; o >>= 1) m = fmaxf(m, __shfl_xor_sync(0xffffffffu, m, o));
        if (t < 256 && lane == 0) sm->wred[wrp] = m;
    }
    __syncthreads();
    if (t < 256) {
        float mloc = fmaxf(sm->wred[2 * g], sm->wred[2 * g + 1]);
        float e = expf(v - mloc);
        #pragma unroll
        for (int o = 16; o; o >>= 1) e += __shfl_xor_sync(0xffffffffu, e, o);
        if (lane == 0) sm->wsum[wrp] = e;
    }
    __syncthreads();
    if (t < 4) {
        float ml = fmaxf(sm->wred[2 * t], sm->wred[2 * t + 1]);
        float sl = sm->wsum[2 * t] + sm->wsum[2 * t + 1];
        unsigned fm0 = mapa_rank(smem_u32(&sm->fm[0][0]), 0);
        unsigned fs0 = mapa_rank(smem_u32(&sm->fs[0][0]), 0);
        stc_f32(fm0 + (unsigned)((rank * GRPB + t) * 4), ml);
        stc_f32(fs0 + (unsigned)((rank * GRPB + t) * 4), sl);
    }
    cluster_sync_();
    if (rank == 0 && t < 4) {
        float mg = sm->fm[0][t];
        #pragma unroll
        for (int r = 1; r < RANKS; r++) mg = fmaxf(mg, sm->fm[r][t]);
        float tot = 0.f;
        #pragma unroll
        for (int r = 0; r < RANKS; r++) tot += sm->fs[r][t] * expf(sm->fm[r][t] - mg);
        g_logz[bbase + t] = mg + logf(tot);
    }
}

// ---------------------------------------------------------------------------
__global__ __launch_bounds__(512) void score_kernel(
    const float* __restrict__ emit,
    const int*   __restrict__ target,
    const void*  __restrict__ mask,
    const float* __restrict__ trans,
    const float* __restrict__ tfs,
    const float* __restrict__ tte)
{
    __shared__ int s_isbyte;
    __shared__ float red[16];
    const int t = threadIdx.x, warp = t >> 5, lane = t & 31;
    if (t == 0) s_isbyte = mask_byte_probe((const unsigned char*)mask);
    __syncthreads();
    const int isbyte = s_isbyte;

    const int idx = blockIdx.x * 512 + t;
    const int i = idx >> 6;
    const int b = idx & 63;

    float contrib = 0.f;
    if (get_mask2(mask, i * BDIM + b, isbyte)) {
        int ti = target[i * BDIM + b];
        contrib = emit[((size_t)i * BDIM + b) * CDIM + ti];
        if (i > 0) {
            int tp = target[(i - 1) * BDIM + b];
            contrib += trans[(size_t)tp * CDIM + ti];
        } else {
            contrib += tfs[ti];
        }
        int nxt = (i + 1 < LDIM) ? get_mask2(mask, (i + 1) * BDIM + b, isbyte) : 0;
        if (!nxt) contrib += tte[ti];
    }
    #pragma unroll
    for (int o = 16; o; o >>= 1) contrib += __shfl_xor_sync(0xffffffffu, contrib, o);
    if (lane == 0) red[warp] = contrib;
    __syncthreads();
    if (t == 0) {
        float s = 0.f;
        #pragma unroll
        for (int w = 0; w < 16; w++) s += red[w];
        g_scorep[blockIdx.x] = s;
    }
}

// ---------------------------------------------------------------------------
__global__ void finalize_kernel(float* __restrict__ out) {
    __shared__ float red[2];
    const int t = threadIdx.x, lane = t & 31, warp = t >> 5;
    float v = (t < BDIM) ? (g_logz[t] - g_scorep[t]) : 0.f;
    #pragma unroll
    for (int o = 16; o; o >>= 1) v += __shfl_xor_sync(0xffffffffu, v, o);
    if (lane == 0) red[warp] = v;
    __syncthreads();
    if (t == 0) out[0] = (red[0] + red[1]) / (float)BDIM;
}

// ---------------------------------------------------------------------------
extern "C" void kernel_launch(void* const* d_in, const int* in_sizes, int n_in,
                              void* d_out, int out_size) {
    const float* emit   = (const float*)d_in[0];
    const int*   target = (const int*)  d_in[1];
    const void*  mask   =               d_in[2];
    const float* trans  = (const float*)d_in[3];
    const float* tfs    = (const float*)d_in[4];
    const float* tte    = (const float*)d_in[5];
    float* out = (float*)d_out;

    cudaFuncSetAttribute(forward_kernel,
                         cudaFuncAttributeMaxDynamicSharedMemorySize, (int)sizeof(SM));

    forward_kernel<<<NCL * RANKS, 512, sizeof(SM)>>>(emit, mask, trans, tfs, tte);
    score_kernel<<<64, 512>>>(emit, target, mask, trans, tfs, tte);
    finalize_kernel<<<1, 64>>>(out);
}

// round 14
// speedup vs baseline: 1.2546x; 1.2546x over previous
#include <cuda_runtime.h>
#include <math.h>
#include <stdint.h>

#define LDIM 512
#define BDIM 64
#define CDIM 512
#define RANKS 8
#define COLS 64           // E-columns / alpha-columns per rank
#define NCL  16           // clusters

__device__ float g_logz[BDIM];
__device__ float g_scorep[BDIM];

// ---------------------------------------------------------------------------
__device__ __forceinline__ unsigned smem_u32(const void* p) {
    return (unsigned)__cvta_generic_to_shared(p);
}
__device__ __forceinline__ unsigned mapa_rank(unsigned saddr, unsigned rank) {
    unsigned r;
    asm("mapa.shared::cluster.u32 %0, %1, %2;" : "=r"(r) : "r"(saddr), "r"(rank));
    return r;
}
__device__ __forceinline__ void stc_f32(unsigned saddr, float v) {
    asm volatile("st.shared::cluster.f32 [%0], %1;" :: "r"(saddr), "f"(v) : "memory");
}
__device__ __forceinline__ void stc_v4(unsigned saddr, float4 v) {
    asm volatile("st.shared::cluster.v4.f32 [%0], {%1,%2,%3,%4};"
                 :: "r"(saddr), "f"(v.x), "f"(v.y), "f"(v.z), "f"(v.w) : "memory");
}
__device__ __forceinline__ void stc_u64(unsigned saddr, unsigned long long v) {
    asm volatile("st.shared::cluster.u64 [%0], %1;" :: "r"(saddr), "l"(v) : "memory");
}
__device__ __forceinline__ void cluster_sync_() {
    asm volatile("barrier.cluster.arrive.aligned;" ::: "memory");
    asm volatile("barrier.cluster.wait.aligned;"   ::: "memory");
}
__device__ __forceinline__ void barh(int id) {   // per-half named barrier
    asm volatile("bar.sync %0, 256;" :: "r"(id) : "memory");
}
__device__ __forceinline__ unsigned long long ffma2(unsigned long long a,
                                                    unsigned long long b,
                                                    unsigned long long c) {
    unsigned long long d;
    asm("fma.rn.f32x2 %0, %1, %2, %3;" : "=l"(d) : "l"(a), "l"(b), "l"(c));
    return d;
}
__device__ __forceinline__ unsigned long long dup2(float v) {
    unsigned long long r; unsigned u = __float_as_uint(v);
    asm("mov.b64 %0, {%1, %1};" : "=l"(r) : "r"(u));
    return r;
}
__device__ __forceinline__ unsigned long long pack2(float lo, float hi) {
    unsigned long long r;
    asm("mov.b64 %0, {%1, %2};" : "=l"(r)
        : "r"(__float_as_uint(lo)), "r"(__float_as_uint(hi)));
    return r;
}
__device__ __forceinline__ float2 unpk(unsigned long long v) {
    unsigned a, b;
    asm("mov.b64 {%0, %1}, %2;" : "=r"(a), "=r"(b) : "l"(v));
    return make_float2(__uint_as_float(a), __uint_as_float(b));
}
__device__ __forceinline__ void mbar_init(unsigned addr, unsigned cnt) {
    asm volatile("mbarrier.init.shared.b64 [%0], %1;" :: "r"(addr), "r"(cnt) : "memory");
}
__device__ __forceinline__ void mbar_arrive_remote(unsigned addr) {
    asm volatile("mbarrier.arrive.release.cluster.shared::cluster.b64 _, [%0];"
                 :: "r"(addr) : "memory");
}
__device__ __forceinline__ void mbar_wait_acq(unsigned addr, unsigned parity) {
    unsigned done;
    asm volatile(
        "{\n\t.reg .pred p;\n\t"
        "mbarrier.try_wait.parity.acquire.cluster.shared::cta.b64 p, [%1], %2;\n\t"
        "selp.b32 %0, 1, 0, p;\n\t}"
        : "=r"(done) : "r"(addr), "r"(parity) : "memory");
    if (!done) {
        asm volatile(
            "{\n\t.reg .pred P1;\n\t"
            "WL_%=:\n\t"
            "mbarrier.try_wait.parity.acquire.cluster.shared::cta.b64 P1, [%0], %1, 0x989680;\n\t"
            "@P1 bra.uni WD_%=;\n\t"
            "bra.uni WL_%=;\n\t"
            "WD_%=:\n\t}"
            :: "r"(addr), "r"(parity) : "memory");
    }
}
__device__ __forceinline__ int mask_byte_probe(const unsigned char* m8) {
    int allnz = 1;
    for (int b = 0; b < BDIM; b++) if (m8[b] == 0) allnz = 0;
    return allnz;
}
__device__ __forceinline__ int get_mask2(const void* mask, int idx, int isbyte) {
    if (isbyte) return ((const unsigned char*)mask)[idx] != 0;
    return ((const int*)mask)[idx] != 0;
}

// ---------------------------------------------------------------------------
struct __align__(16) SM {
    float  E[CDIM * COLS];           // 128 KB  exp(trans) col-slice (shared R/O)
    float2 pbuf[2][2][CDIM];         // 16 KB   [half][par][state] -> {p_b0, p_b1}
    float  part[2][16][2][COLS];     // 16 KB   [half][seg][b][col]
    float2 stage[2][COLS];           // 1 KB    [half][col] -> {p_b0, p_b1}
    float2 pmail[2][2][RANKS];       // 512 B   [half][par][src] lagged maxes
    float  wredH[2][4];              // per-half warp maxes (mail source)
    float  wred_f[4][2], wsum_f[4][2];
    float  fm[RANKS][4], fs[RANKS][4];
    unsigned long long mbar[2][2];   // [half][par], arrive count 8
    unsigned char act2[2][LDIM][2];  // [half][i][local batch]
    unsigned char anyH[2][LDIM];
    int isbyte;
};

__global__ void __cluster_dims__(RANKS, 1, 1) __launch_bounds__(512, 1)
forward_kernel(const float* __restrict__ emit,
               const void*  __restrict__ mask,
               const float* __restrict__ trans,
               const float* __restrict__ tfs,
               const float* __restrict__ tte)
{
    extern __shared__ char smraw[];
    SM* sm = (SM*)smraw;

    const int t     = threadIdx.x;
    const int cta   = blockIdx.x;
    const int rank  = cta & (RANKS - 1);
    const int cl    = cta >> 3;
    const int bbase = cl * 4;

    const int H    = t >> 8;              // half (independent pipeline)
    const int h_t  = t & 255;             // thread-in-half
    const int lane = t & 31;
    const int wih  = h_t >> 5;            // warp-in-half (0..7)

    // owner mapping (h_t < 128): 2 batches x 64 cols
    const int bloc = (h_t >> 6) & 1;
    const int col  = h_t & 63;
    const int b_glob  = bbase + H * 2 + bloc;
    const int cg_glob = rank * COLS + col;

    // matvec mapping (all 256 of half): cg = 4-col group, seg = 32-row segment
    const int cg  = h_t & 15;
    const int seg = h_t >> 4;              // 0..15

    if (t == 0) {
        sm->isbyte = mask_byte_probe((const unsigned char*)mask);
        mbar_init(smem_u32(&sm->mbar[0][0]), RANKS);
        mbar_init(smem_u32(&sm->mbar[0][1]), RANKS);
        mbar_init(smem_u32(&sm->mbar[1][0]), RANKS);
        mbar_init(smem_u32(&sm->mbar[1][1]), RANKS);
    }

    // ---- E slice = exp(trans[:, rank*64 .. +64]) (shared by both halves) ----
    for (int idx = t; idx < CDIM * COLS; idx += 512) {
        int row = idx >> 6, c = idx & 63;
        sm->E[idx] = expf(trans[(size_t)row * CDIM + rank * COLS + c]);
    }
    __syncthreads();

    // ---- mask flags (one i per thread) ----
    const int isbyte = sm->isbyte;
    {
        int i = t;
        int m0 = get_mask2(mask, i * BDIM + bbase + 0, isbyte);
        int m1 = get_mask2(mask, i * BDIM + bbase + 1, isbyte);
        int m2 = get_mask2(mask, i * BDIM + bbase + 2, isbyte);
        int m3 = get_mask2(mask, i * BDIM + bbase + 3, isbyte);
        sm->act2[0][i][0] = (unsigned char)m0;
        sm->act2[0][i][1] = (unsigned char)m1;
        sm->act2[1][i][0] = (unsigned char)m2;
        sm->act2[1][i][1] = (unsigned char)m3;
        sm->anyH[0][i] = (unsigned char)(m0 | m1);
        sm->anyH[1][i] = (unsigned char)(m2 | m3);
    }

    // ---- alpha_0 + warp maxes ----
    float a = 0.f, m_used = 0.f;
    if (h_t < 128) {
        a = emit[(size_t)b_glob * CDIM + cg_glob] + tfs[cg_glob];
        float m = a;
        #pragma unroll
        for (int o = 16; o; o >>= 1) m = fmaxf(m, __shfl_xor_sync(0xffffffffu, m, o));
        if (lane == 0) {
            sm->wred_f[H * 2 + bloc][(h_t >> 5) & 1] = m;
            sm->wredH[H][h_t >> 5] = m;
        }
    }
    __syncthreads();

    // ---- prologue: exact global max of alpha_0 (publishes mbar inits too) ----
    if (t < 32) {
        int dr = t >> 2, dg = t & 3;
        float ml = fmaxf(sm->wred_f[dg][0], sm->wred_f[dg][1]);
        stc_f32(mapa_rank(smem_u32(&sm->fm[0][0]), dr) + (unsigned)((rank * 4 + dg) * 4), ml);
    }
    cluster_sync_();
    if (h_t < 128) {
        float mg = sm->fm[0][H * 2 + bloc];
        #pragma unroll
        for (int r = 1; r < RANKS; r++) mg = fmaxf(mg, sm->fm[r][H * 2 + bloc]);
        m_used = mg;
        ((float*)&sm->stage[H][col])[bloc] = __expf(a - mg);
    }
    __syncthreads();

    // per-thread push targets (warp wih ships to rank wih)
    const unsigned p_dst = mapa_rank(smem_u32(&sm->pbuf[H][0][0]), wih);
    const unsigned m_dst = mapa_rank(smem_u32(&sm->pmail[H][0][0]), wih);
    const unsigned b_dst = mapa_rank(smem_u32(&sm->mbar[H][0]), wih);
    const unsigned bar_l = smem_u32(&sm->mbar[H][0]);

    int uses = 0;
    for (int i = 1; i < LDIM; i++) {
        if (!sm->anyH[H][i]) continue;          // uniform within half
        const int par = uses & 1, ph = (uses >> 1) & 1;

        // emit prefetch (consumed in combine)
        float e_reg = 0.f;
        if (h_t < 128) e_reg = emit[((size_t)i * BDIM + b_glob) * CDIM + cg_glob];

        // ---- push: warp wih ships this half's p (512B) + mail to rank wih ----
        {
            float4 pv = ((const float4*)&sm->stage[H][0])[lane];
            stc_v4(p_dst + (unsigned)(par * 4096 + rank * 512 + lane * 16), pv);
            if (lane == 0) {
                float ml0 = fmaxf(sm->wredH[H][0], sm->wredH[H][1]);
                float ml1 = fmaxf(sm->wredH[H][2], sm->wredH[H][3]);
                stc_u64(m_dst + (unsigned)(par * 64 + rank * 8), pack2(ml0, ml1));
            }
            __syncwarp();
            if (lane == 0) mbar_arrive_remote(b_dst + (unsigned)(par * 8));
        }

        // ---- wait for all 8 ranks' slices (this half only) ----
        mbar_wait_acq(bar_l + (unsigned)(par * 8), (unsigned)ph);

        // ---- matvec: E (SMEM, shared) x p (this half), 2 batches ----
        {
            const ulonglong2* Ev = (const ulonglong2*)sm->E + seg * 32 * 16 + cg;
            const float2*     pv = &sm->pbuf[H][par][seg * 32];
            unsigned long long ac00 = 0, ac01 = 0, ac10 = 0, ac11 = 0;
            #pragma unroll
            for (int c = 0; c < 32; c++) {
                ulonglong2 e  = Ev[c * 16];
                float2     pq = pv[c];
                unsigned long long d0 = dup2(pq.x), d1 = dup2(pq.y);
                ac00 = ffma2(d0, e.x, ac00); ac01 = ffma2(d0, e.y, ac01);
                ac10 = ffma2(d1, e.x, ac10); ac11 = ffma2(d1, e.y, ac11);
            }
            float2 lo = unpk(ac00), hi = unpk(ac01);
            *(float4*)&sm->part[H][seg][0][cg * 4] = make_float4(lo.x, lo.y, hi.x, hi.y);
            lo = unpk(ac10); hi = unpk(ac11);
            *(float4*)&sm->part[H][seg][1][cg * 4] = make_float4(lo.x, lo.y, hi.x, hi.y);
        }
        barh(H + 1);

        // ---- combine: sum 16 segs, update alpha, stage next p + mail ----
        if (h_t < 128) {
            float s = 0.f;
            #pragma unroll
            for (int sg = 0; sg < 16; sg += 4)
                s += (sm->part[H][sg][bloc][col]     + sm->part[H][sg + 1][bloc][col])
                   + (sm->part[H][sg + 2][bloc][col] + sm->part[H][sg + 3][bloc][col]);
            float m_next = ((const float*)&sm->pmail[H][par][0])[bloc];
            #pragma unroll
            for (int r = 1; r < RANKS; r++)
                m_next = fmaxf(m_next, ((const float*)&sm->pmail[H][par][r])[bloc]);
            float anew = m_used + __logf(s) + e_reg;
            if (sm->act2[H][i][bloc]) a = anew;
            m_used = m_next;
            ((float*)&sm->stage[H][col])[bloc] = __expf(a - m_next);
            float m = a;
            #pragma unroll
            for (int o = 16; o; o >>= 1) m = fmaxf(m, __shfl_xor_sync(0xffffffffu, m, o));
            if (lane == 0) sm->wredH[H][h_t >> 5] = m;
        }
        barh(H + 1);
        uses++;
    }

    __syncthreads();   // halves rejoin

    // ---- final: log_z = logsumexp(alpha + tte) across 8 ranks ----
    float v = -3.4e38f;
    if (h_t < 128) {
        v = a + tte[cg_glob];
        float m = v;
        #pragma unroll
        for (int o = 16; o; o >>= 1) m = fmaxf(m, __shfl_xor_sync(0xffffffffu, m, o));
        if (lane == 0) sm->wred_f[H * 2 + bloc][(h_t >> 5) & 1] = m;
    }
    __syncthreads();
    if (h_t < 128) {
        float mloc = fmaxf(sm->wred_f[H * 2 + bloc][0], sm->wred_f[H * 2 + bloc][1]);
        float e = expf(v - mloc);
        #pragma unroll
        for (int o = 16; o; o >>= 1) e += __shfl_xor_sync(0xffffffffu, e, o);
        if (lane == 0) sm->wsum_f[H * 2 + bloc][(h_t >> 5) & 1] = e;
    }
    __syncthreads();
    if (t < 4) {
        float ml = fmaxf(sm->wred_f[t][0], sm->wred_f[t][1]);
        float sl = sm->wsum_f[t][0] + sm->wsum_f[t][1];
        unsigned fm0 = mapa_rank(smem_u32(&sm->fm[0][0]), 0);
        unsigned fs0 = mapa_rank(smem_u32(&sm->fs[0][0]), 0);
        stc_f32(fm0 + (unsigned)((rank * 4 + t) * 4), ml);
        stc_f32(fs0 + (unsigned)((rank * 4 + t) * 4), sl);
    }
    cluster_sync_();
    if (rank == 0 && t < 4) {
        float mg = sm->fm[0][t];
        #pragma unroll
        for (int r = 1; r < RANKS; r++) mg = fmaxf(mg, sm->fm[r][t]);
        float tot = 0.f;
        #pragma unroll
        for (int r = 0; r < RANKS; r++) tot += sm->fs[r][t] * expf(sm->fm[r][t] - mg);
        g_logz[bbase + t] = mg + logf(tot);
    }
}

// ---------------------------------------------------------------------------
__global__ __launch_bounds__(512) void score_kernel(
    const float* __restrict__ emit,
    const int*   __restrict__ target,
    const void*  __restrict__ mask,
    const float* __restrict__ trans,
    const float* __restrict__ tfs,
    const float* __restrict__ tte)
{
    __shared__ int s_isbyte;
    __shared__ float red[16];
    const int t = threadIdx.x, warp = t >> 5, lane = t & 31;
    if (t == 0) s_isbyte = mask_byte_probe((const unsigned char*)mask);
    __syncthreads();
    const int isbyte = s_isbyte;

    const int idx = blockIdx.x * 512 + t;
    const int i = idx >> 6;
    const int b = idx & 63;

    float contrib = 0.f;
    if (get_mask2(mask, i * BDIM + b, isbyte)) {
        int ti = target[i * BDIM + b];
        contrib = emit[((size_t)i * BDIM + b) * CDIM + ti];
        if (i > 0) {
            int tp = target[(i - 1) * BDIM + b];
            contrib += trans[(size_t)tp * CDIM + ti];
        } else {
            contrib += tfs[ti];
        }
        int nxt = (i + 1 < LDIM) ? get_mask2(mask, (i + 1) * BDIM + b, isbyte) : 0;
        if (!nxt) contrib += tte[ti];
    }
    #pragma unroll
    for (int o = 16; o; o >>= 1) contrib += __shfl_xor_sync(0xffffffffu, contrib, o);
    if (lane == 0) red[warp] = contrib;
    __syncthreads();
    if (t == 0) {
        float s = 0.f;
        #pragma unroll
        for (int w = 0; w < 16; w++) s += red[w];
        g_scorep[blockIdx.x] = s;
    }
}

// ---------------------------------------------------------------------------
__global__ void finalize_kernel(float* __restrict__ out) {
    __shared__ float red[2];
    const int t = threadIdx.x, lane = t & 31, warp = t >> 5;
    float v = (t < BDIM) ? (g_logz[t] - g_scorep[t]) : 0.f;
    #pragma unroll
    for (int o = 16; o; o >>= 1) v += __shfl_xor_sync(0xffffffffu, v, o);
    if (lane == 0) red[warp] = v;
    __syncthreads();
    if (t == 0) out[0] = (red[0] + red[1]) / (float)BDIM;
}

// ---------------------------------------------------------------------------
extern "C" void kernel_launch(void* const* d_in, const int* in_sizes, int n_in,
                              void* d_out, int out_size) {
    const float* emit   = (const float*)d_in[0];
    const int*   target = (const int*)  d_in[1];
    const void*  mask   =               d_in[2];
    const float* trans  = (const float*)d_in[3];
    const float* tfs    = (const float*)d_in[4];
    const float* tte    = (const float*)d_in[5];
    float* out = (float*)d_out;

    cudaFuncSetAttribute(forward_kernel,
                         cudaFuncAttributeMaxDynamicSharedMemorySize, (int)sizeof(SM));

    forward_kernel<<<NCL * RANKS, 512, sizeof(SM)>>>(emit, mask, trans, tfs, tte);
    score_kernel<<<64, 512>>>(emit, target, mask, trans, tfs, tte);
    finalize_kernel<<<1, 64>>>(out);
}